// round 11
// baseline (speedup 1.0000x reference)
#include <cuda_runtime.h>
#include <cuda_bf16.h>
#include <math.h>
#include <stdint.h>

// Problem constants
#define BB 2
#define NN 1024
#define CC 512
#define HH 8
#define HD 64
#define NCLUS 8
#define SCALE 0.125f
#define EPS 1e-6f
#define EPS_N (1e-6f/1024.0f)
#define SC_CAP 256                                 // max cluster size assumed (12+ sigma)

#define OUT_ELEMS (BB*NN*CC)                       // 1,048,576
#define MAP_ELEMS ((size_t)BB*NCLUS*HH*NN*NN)      // 134,217,728

// Scratch (static device globals; no allocation allowed)
__device__ float g_Q[BB*NN*CC];
__device__ float g_Kb[BB*NN*CC];
__device__ float g_V[BB*NN*CC];
__device__ float g_O[BB*NN*CC];
__device__ float g_colsum[BB*CC];
__device__ float g_csp[8][BB*CC];                  // colsum partials
__device__ int   g_mem[BB*NCLUS*NN];
__device__ int   g_cnt[BB*NCLUS];
__device__ float g_Sc[(size_t)BB*NCLUS*HH*SC_CAP*SC_CAP];  // compact masked scores

// ---------------------------------------------------------------------------
// Deterministic cluster compaction: one warp per (b,c).
// ---------------------------------------------------------------------------
__global__ void compact_kernel(const int* __restrict__ idx,
                               int* __restrict__ mem, int* __restrict__ cnt)
{
    const int bc = blockIdx.x;
    const int b = bc >> 3, c = bc & 7;
    const int lane = threadIdx.x;
    int pos = 0;
    for (int t0 = 0; t0 < NN; t0 += 32) {
        int t = t0 + lane;
        int v = idx[b * NN + t];
        unsigned ball = __ballot_sync(0xffffffffu, v == c);
        if (v == c) {
            int r = __popc(ball & ((1u << lane) - 1u));
            mem[bc * NN + pos + r] = t;
        }
        pos += __popc(ball);
    }
    if (lane == 0) cnt[bc] = pos;
}

// ---------------------------------------------------------------------------
// Zero all NON-member rows of the map. Depends only on idx -> forks at graph
// root, overlaps the whole compute chain. Grid-stride over (bch, i-chunk)
// work items; each item = 64 rows of 4KB, one float4 per thread per row.
// Member rows (idx[b,i]==c) are skipped; compose_rows writes them later.
// ---------------------------------------------------------------------------
__global__ void __launch_bounds__(256) zero_rows(const int* __restrict__ idx,
                                                 float* __restrict__ map)
{
    const int nitems = 128 * 16;           // bch * i-chunks
    __shared__ int sidx[64];
    for (int item = blockIdx.x; item < nitems; item += gridDim.x) {
        const int bch = item >> 4;         // 0..127
        const int chunk = item & 15;       // 0..15
        const int b = bch >> 6;            // bch = ((b*8+c)*8+h)
        const int c = (bch >> 3) & 7;
        const int i0 = chunk * 64;

        if (threadIdx.x < 64)
            sidx[threadIdx.x] = idx[b * NN + i0 + threadIdx.x];
        __syncthreads();

        const float4 z = make_float4(0.f, 0.f, 0.f, 0.f);
        float4* base = reinterpret_cast<float4*>(map + ((size_t)bch * NN + i0) * NN);
        #pragma unroll 4
        for (int r = 0; r < 64; r++) {
            if (sidx[r] != c)
                __stcs(&base[(size_t)r * (NN / 4) + threadIdx.x], z);
        }
        __syncthreads();
    }
}

// ---------------------------------------------------------------------------
// Compose cluster member rows of the map: full 4KB row = zeros + Sc values at
// member columns, written once, coalesced.
// ---------------------------------------------------------------------------
__global__ void __launch_bounds__(128) compose_rows(
    const float* __restrict__ Sc, const int* __restrict__ mem,
    const int* __restrict__ cnt, float* __restrict__ map)
{
    const int bch = blockIdx.y;          // 128
    const int bc = bch >> 3;
    int Mc = cnt[bc]; if (Mc > SC_CAP) Mc = SC_CAP;
    const int p = blockIdx.x;            // row within cluster
    if (p >= Mc) return;

    __shared__ float rowbuf[NN];
    #pragma unroll
    for (int j = threadIdx.x; j < NN; j += 128) rowbuf[j] = 0.f;
    __syncthreads();

    const float* src = Sc + ((size_t)bch * SC_CAP + p) * SC_CAP;
    const int* memb = mem + bc * NN;
    for (int q = threadIdx.x; q < Mc; q += 128)
        rowbuf[memb[q]] = src[q];
    __syncthreads();

    const int i = memb[p];
    float4* dst = reinterpret_cast<float4*>(map + ((size_t)bch * NN + i) * NN);
    const float4* s4 = reinterpret_cast<const float4*>(rowbuf);
    #pragma unroll
    for (int j = threadIdx.x; j < NN / 4; j += 128)
        __stcs(&dst[j], s4[j]);
}

// ---------------------------------------------------------------------------
// TF32 helpers (3xTF32 split for ~fp32 accuracy on tensor cores)
// ---------------------------------------------------------------------------
__device__ __forceinline__ void tf32_pair(float x, uint32_t& hi, uint32_t& lo)
{
    asm("cvt.rna.tf32.f32 %0, %1;" : "=r"(hi) : "f"(x));
    float r = x - __uint_as_float(hi);
    asm("cvt.rna.tf32.f32 %0, %1;" : "=r"(lo) : "f"(r));
}

__device__ __forceinline__ void mma8(float* c, const uint32_t* a, const uint32_t* b)
{
    asm volatile(
        "mma.sync.aligned.m16n8k8.row.col.f32.tf32.tf32.f32 "
        "{%0,%1,%2,%3}, {%4,%5,%6,%7}, {%8,%9}, {%0,%1,%2,%3};"
        : "+f"(c[0]), "+f"(c[1]), "+f"(c[2]), "+f"(c[3])
        : "r"(a[0]), "r"(a[1]), "r"(a[2]), "r"(a[3]), "r"(b[0]), "r"(b[1]));
}

// ---------------------------------------------------------------------------
// TF32 GEMM body: out[m,n] = sum_k X[m,k]*W[n,k] (+bias). K=N=512.
// Block tile 128x128, BK=16, 8 warps (2x4) of 64x32, 3xTF32.
// ---------------------------------------------------------------------------
#define SMS 136

__device__ __forceinline__ void gemm_tf32_body(
    const float* __restrict__ X, const float* __restrict__ W,
    const float* __restrict__ bias, float* __restrict__ out,
    int m0, int n0, bool has_bias)
{
    __shared__ uint32_t As_h[16][SMS], As_l[16][SMS];
    __shared__ uint32_t Bs_h[16][SMS], Bs_l[16][SMS];

    const int tid  = threadIdx.x;
    const int lane = tid & 31;
    const int wid  = tid >> 5;
    const int warp_m = wid & 1;
    const int warp_n = wid >> 1;

    const int lr  = tid >> 1;
    const int lc0 = (tid & 1) * 8;

    float acc[4][4][4];
    #pragma unroll
    for (int f = 0; f < 4; f++)
        #pragma unroll
        for (int g = 0; g < 4; g++)
            #pragma unroll
            for (int e = 0; e < 4; e++) acc[f][g][e] = 0.f;

    for (int k0 = 0; k0 < 512; k0 += 16) {
        #pragma unroll
        for (int u = 0; u < 2; u++) {
            float4 va = *reinterpret_cast<const float4*>(&X[(size_t)(m0 + lr) * 512 + k0 + lc0 + u * 4]);
            float ea[4] = {va.x, va.y, va.z, va.w};
            float4 vb = *reinterpret_cast<const float4*>(&W[(size_t)(n0 + lr) * 512 + k0 + lc0 + u * 4]);
            float eb[4] = {vb.x, vb.y, vb.z, vb.w};
            #pragma unroll
            for (int j = 0; j < 4; j++) {
                int k = lc0 + u * 4 + j;
                uint32_t h, l;
                tf32_pair(ea[j], h, l);
                As_h[k][lr] = h; As_l[k][lr] = l;
                tf32_pair(eb[j], h, l);
                Bs_h[k][lr] = h; Bs_l[k][lr] = l;
            }
        }
        __syncthreads();

        #pragma unroll
        for (int ks = 0; ks < 2; ks++) {
            const int kb = ks * 8 + (lane & 3);
            uint32_t ah[4][4], al[4][4];
            #pragma unroll
            for (int f = 0; f < 4; f++) {
                int m = warp_m * 64 + f * 16 + (lane >> 2);
                ah[f][0] = As_h[kb][m];     ah[f][1] = As_h[kb][m + 8];
                ah[f][2] = As_h[kb + 4][m]; ah[f][3] = As_h[kb + 4][m + 8];
                al[f][0] = As_l[kb][m];     al[f][1] = As_l[kb][m + 8];
                al[f][2] = As_l[kb + 4][m]; al[f][3] = As_l[kb + 4][m + 8];
            }
            uint32_t bh[4][2], bl[4][2];
            #pragma unroll
            for (int g = 0; g < 4; g++) {
                int n = warp_n * 32 + g * 8 + (lane >> 2);
                bh[g][0] = Bs_h[kb][n]; bh[g][1] = Bs_h[kb + 4][n];
                bl[g][0] = Bs_l[kb][n]; bl[g][1] = Bs_l[kb + 4][n];
            }
            #pragma unroll
            for (int f = 0; f < 4; f++)
                #pragma unroll
                for (int g = 0; g < 4; g++) {
                    mma8(acc[f][g], ah[f], bh[g]);
                    mma8(acc[f][g], ah[f], bl[g]);
                    mma8(acc[f][g], al[f], bh[g]);
                }
        }
        __syncthreads();
    }

    #pragma unroll
    for (int f = 0; f < 4; f++) {
        const int m = m0 + warp_m * 64 + f * 16 + (lane >> 2);
        #pragma unroll
        for (int g = 0; g < 4; g++) {
            const int n = n0 + warp_n * 32 + g * 8 + (lane & 3) * 2;
            float b0 = 0.f, b1 = 0.f;
            if (has_bias) { b0 = bias[n]; b1 = bias[n + 1]; }
            float2 v0 = make_float2(acc[f][g][0] + b0, acc[f][g][1] + b1);
            float2 v1 = make_float2(acc[f][g][2] + b0, acc[f][g][3] + b1);
            *reinterpret_cast<float2*>(&out[(size_t)m * 512 + n]) = v0;
            *reinterpret_cast<float2*>(&out[(size_t)(m + 8) * 512 + n]) = v1;
        }
    }
}

__global__ void __launch_bounds__(256) gemm_qkv_tf32(
    const float* __restrict__ X,
    const float* __restrict__ Wq, const float* __restrict__ Wk, const float* __restrict__ Wv,
    float* __restrict__ Qo, float* __restrict__ Ko, float* __restrict__ Vo)
{
    const float* W = (blockIdx.z == 0) ? Wq : (blockIdx.z == 1) ? Wk : Wv;
    float* out     = (blockIdx.z == 0) ? Qo : (blockIdx.z == 1) ? Ko : Vo;
    gemm_tf32_body(X, W, nullptr, out, blockIdx.y * 128, blockIdx.x * 128, false);
}

__global__ void __launch_bounds__(256) gemm_proj_tf32(
    const float* __restrict__ X, const float* __restrict__ W,
    const float* __restrict__ bias, float* __restrict__ out)
{
    gemm_tf32_body(X, W, bias, out, blockIdx.y * 128, blockIdx.x * 128, true);
}

// ---------------------------------------------------------------------------
// Column sums of V, two-stage deterministic.
// Stage 1: grid (2, BB, 8): 256 cols/block, 128-row slab per z. Coalesced.
// Stage 2: sum the 8 partials.
// ---------------------------------------------------------------------------
__global__ void __launch_bounds__(256) colsum_part(const float* __restrict__ V,
                                                   float (*__restrict__ csp)[BB*CC])
{
    const int b = blockIdx.y;
    const int z = blockIdx.z;
    const int c = blockIdx.x * 256 + threadIdx.x;
    const float* base = V + ((size_t)b * NN + z * 128) * CC + c;
    float s = 0.0f;
    #pragma unroll 8
    for (int n = 0; n < 128; n++)
        s += base[(size_t)n * CC];
    csp[z][b * CC + c] = s;
}

__global__ void __launch_bounds__(256) colsum_final(const float (*__restrict__ csp)[BB*CC],
                                                    float* __restrict__ cs)
{
    const int i = blockIdx.x * 256 + threadIdx.x;   // 0..BB*CC-1
    float s = 0.0f;
    #pragma unroll
    for (int z = 0; z < 8; z++) s += csp[z][i];
    cs[i] = s;
}

// ---------------------------------------------------------------------------
// Fused cluster-block attention (compact). Writes compact scores Sc and O.
// ---------------------------------------------------------------------------
extern __shared__ float sm_dyn[];
__global__ void cluster_attn(const float* __restrict__ Q, const float* __restrict__ K,
                             const float* __restrict__ V,
                             const int* __restrict__ mem, const int* __restrict__ cnt,
                             const float* __restrict__ cs,
                             float* __restrict__ Sc, float* __restrict__ O)
{
    const int bch = blockIdx.y;
    const int h  = bch & 7;
    const int bc = bch >> 3;
    const int b  = bc >> 3;
    const int Mc = cnt[bc];
    const int ti = blockIdx.x;
    if (ti * 64 >= Mc) return;

    float* Qs = sm_dyn;                 // [k][i], 64x64
    float* Ks = Qs + 4096;              // [k][j]
    float* Vs = Ks + 4096;              // [j][d]
    float* Es = Vs + 4096;              // [i][j], 64x65

    const int t = threadIdx.x;
    const int row = t >> 2, quad = t & 3;
    const int tx = t & 15, ty = t >> 4;

    const int* memb = mem + bc * NN;

    const int il_row = ti * 64 + row;
    const int gi_row = (il_row < Mc) ? memb[il_row] : -1;
    {
        const float* qb = (gi_row >= 0)
            ? Q + ((size_t)(b * NN + gi_row)) * CC + h * HD : nullptr;
        #pragma unroll
        for (int u = 0; u < 4; u++) {
            int k = quad * 16 + u * 4;
            float4 qv = qb ? *reinterpret_cast<const float4*>(qb + k)
                           : make_float4(0.f, 0.f, 0.f, 0.f);
            Qs[(k+0)*64 + row] = qv.x; Qs[(k+1)*64 + row] = qv.y;
            Qs[(k+2)*64 + row] = qv.z; Qs[(k+3)*64 + row] = qv.w;
        }
    }

    int gi_r[4];
    #pragma unroll
    for (int r = 0; r < 4; r++) {
        int il = ti * 64 + ty * 4 + r;
        gi_r[r] = (il < Mc) ? memb[il] : -1;
    }

    float acc2[4][4] = {};
    float rsum[4] = {0.f, 0.f, 0.f, 0.f};

    const int njt = (Mc + 63) >> 6;
    for (int jb = 0; jb < njt; jb++) {
        const int jl_row = jb * 64 + row;
        const int gj_row = (jl_row < Mc) ? memb[jl_row] : -1;
        const float* kb = (gj_row >= 0)
            ? K + ((size_t)(b * NN + gj_row)) * CC + h * HD : nullptr;
        const float* vb = (gj_row >= 0)
            ? V + ((size_t)(b * NN + gj_row)) * CC + h * HD : nullptr;
        #pragma unroll
        for (int u = 0; u < 4; u++) {
            int k = quad * 16 + u * 4;
            float4 kv = kb ? *reinterpret_cast<const float4*>(kb + k)
                           : make_float4(0.f, 0.f, 0.f, 0.f);
            Ks[(k+0)*64 + row] = kv.x; Ks[(k+1)*64 + row] = kv.y;
            Ks[(k+2)*64 + row] = kv.z; Ks[(k+3)*64 + row] = kv.w;
            float4 vv = vb ? *reinterpret_cast<const float4*>(vb + k)
                           : make_float4(0.f, 0.f, 0.f, 0.f);
            *reinterpret_cast<float4*>(&Vs[row * 64 + k]) = vv;
        }
        __syncthreads();

        // gemm1: S = Q K^T
        float acc[4][4] = {};
        #pragma unroll
        for (int kk = 0; kk < 64; kk++) {
            float4 af = *reinterpret_cast<const float4*>(&Qs[kk*64 + ty*4]);
            float4 bf = *reinterpret_cast<const float4*>(&Ks[kk*64 + tx*4]);
            float ar[4] = {af.x, af.y, af.z, af.w};
            float br[4] = {bf.x, bf.y, bf.z, bf.w};
            #pragma unroll
            for (int r = 0; r < 4; r++)
                #pragma unroll
                for (int c = 0; c < 4; c++)
                    acc[r][c] += ar[r] * br[c];
        }

        // epilogue: scale, exp, compact-store, stage E
        #pragma unroll
        for (int r = 0; r < 4; r++) {
            const int pi = ti * 64 + ty * 4 + r;
            const bool vr = (gi_r[r] >= 0);
            #pragma unroll
            for (int c = 0; c < 4; c++) {
                const int qj = jb * 64 + tx * 4 + c;
                const bool valid = vr && (qj < Mc);
                float s = acc[r][c] * SCALE;
                float e = (valid && s != 0.0f) ? __expf(s) : 0.0f;
                if (valid && Sc != nullptr)
                    Sc[((size_t)bch * SC_CAP + pi) * SC_CAP + qj] = s;
                Es[(ty*4 + r) * 65 + tx*4 + c] = e;
                rsum[r] += e;
            }
        }
        __syncthreads();

        // gemm2: acc2 += E @ V
        #pragma unroll
        for (int jj = 0; jj < 64; jj++) {
            float ar[4];
            #pragma unroll
            for (int r = 0; r < 4; r++) ar[r] = Es[(ty*4 + r) * 65 + jj];
            float4 bv = *reinterpret_cast<const float4*>(&Vs[jj * 64 + tx*4]);
            float br[4] = {bv.x, bv.y, bv.z, bv.w};
            #pragma unroll
            for (int r = 0; r < 4; r++)
                #pragma unroll
                for (int c = 0; c < 4; c++)
                    acc2[r][c] += ar[r] * br[c];
        }
        __syncthreads();
    }

    #pragma unroll
    for (int r = 0; r < 4; r++) {
        #pragma unroll
        for (int o = 1; o < 16; o <<= 1)
            rsum[r] += __shfl_xor_sync(0xffffffffu, rsum[r], o);
    }

    #pragma unroll
    for (int r = 0; r < 4; r++) {
        if (gi_r[r] < 0) continue;
        float inv = 1.0f / (rsum[r] + EPS);
        float4 o;
        float* po = &o.x;
        #pragma unroll
        for (int c = 0; c < 4; c++) {
            int d = tx * 4 + c;
            po[c] = (acc2[r][c] + EPS_N * cs[b * CC + h * HD + d]) * inv;
        }
        *reinterpret_cast<float4*>(&O[((size_t)(b * NN + gi_r[r])) * CC + h * HD + tx*4]) = o;
    }
}

// ---------------------------------------------------------------------------
extern "C" void kernel_launch(void* const* d_in, const int* in_sizes, int n_in,
                              void* d_out, int out_size)
{
    const float* x_token = nullptr;
    const int*   idx     = nullptr;
    const float* Wmat[4] = {nullptr, nullptr, nullptr, nullptr};  // Wq,Wk,Wv,Wproj
    const float* bproj   = nullptr;
    int nW = 0;
    for (int i = 0; i < n_in; i++) {
        int s = in_sizes[i];
        if (s == OUT_ELEMS && !x_token)      x_token = (const float*)d_in[i];
        else if (s == 262144 && nW < 4)      Wmat[nW++] = (const float*)d_in[i];
        else if (s == 2048 && !idx)          idx = (const int*)d_in[i];
        else if (s == 512 && !bproj)         bproj = (const float*)d_in[i];
    }

    float *pQ, *pK, *pV, *pO, *pCS, *pSc;
    float (*pCSP)[BB*CC];
    int *pMem, *pCnt;
    cudaGetSymbolAddress((void**)&pQ,   g_Q);
    cudaGetSymbolAddress((void**)&pK,   g_Kb);
    cudaGetSymbolAddress((void**)&pV,   g_V);
    cudaGetSymbolAddress((void**)&pO,   g_O);
    cudaGetSymbolAddress((void**)&pCS,  g_colsum);
    cudaGetSymbolAddress((void**)&pCSP, g_csp);
    cudaGetSymbolAddress((void**)&pMem, g_mem);
    cudaGetSymbolAddress((void**)&pCnt, g_cnt);
    cudaGetSymbolAddress((void**)&pSc,  g_Sc);

    float* out = (float*)d_out;
    const bool has_map = ((size_t)out_size >= OUT_ELEMS + MAP_ELEMS);
    float* map = has_map ? out + OUT_ELEMS : nullptr;

    static cudaStream_t s2 = nullptr;
    static cudaEvent_t evStart = nullptr, evAttn = nullptr, evEnd = nullptr;
    if (!s2) {
        cudaStreamCreateWithFlags(&s2, cudaStreamNonBlocking);
        cudaEventCreateWithFlags(&evStart, cudaEventDisableTiming);
        cudaEventCreateWithFlags(&evAttn,  cudaEventDisableTiming);
        cudaEventCreateWithFlags(&evEnd,   cudaEventDisableTiming);
        const int SMEM_BYTES = (3 * 4096 + 64 * 65) * sizeof(float);  // 65792
        cudaFuncSetAttribute(cluster_attn,
                             cudaFuncAttributeMaxDynamicSharedMemorySize, SMEM_BYTES);
    }
    const int SMEM_BYTES = (3 * 4096 + 64 * 65) * sizeof(float);

    // Fork at graph root: zero the NON-member rows only (depends on idx input
    // alone, not on any compute). 470MB of the 537MB map, written exactly once.
    if (has_map) {
        cudaEventRecord(evStart, 0);
        cudaStreamWaitEvent(s2, evStart, 0);
        zero_rows<<<1024, 256, 0, s2>>>(idx, map);
    }

    // Main stream: compaction -> QKV (tf32) -> colsum -> attention.
    compact_kernel<<<BB * NCLUS, 32>>>(idx, pMem, pCnt);
    gemm_qkv_tf32<<<dim3(4, 16, 3), 256>>>(x_token, Wmat[0], Wmat[1], Wmat[2], pQ, pK, pV);
    colsum_part<<<dim3(CC / 256, BB, 8), 256>>>(pV, pCSP);
    colsum_final<<<(BB * CC) / 256, 256>>>(pCSP, pCS);
    cluster_attn<<<dim3(SC_CAP / 64, BB * NCLUS * HH), 256, SMEM_BYTES>>>(
        pQ, pK, pV, pMem, pCnt, pCS, has_map ? pSc : nullptr, pO);

    if (has_map) {
        // s2: after zero_rows AND attention, write the member rows.
        cudaEventRecord(evAttn, 0);
        cudaStreamWaitEvent(s2, evAttn, 0);
        compose_rows<<<dim3(SC_CAP, BB * NCLUS * HH), 128, 0, s2>>>(pSc, pMem, pCnt, map);
        cudaEventRecord(evEnd, s2);
    }

    // Output projection (concurrent with compose_rows).
    gemm_proj_tf32<<<dim3(4, 16), 256>>>(pO, Wmat[3], bproj, out);

    if (has_map)
        cudaStreamWaitEvent(0, evEnd, 0);   // join before capture ends
}

// round 12
// speedup vs baseline: 1.4340x; 1.4340x over previous
#include <cuda_runtime.h>
#include <cuda_bf16.h>
#include <math.h>
#include <stdint.h>

// Problem constants
#define BB 2
#define NN 1024
#define CC 512
#define HH 8
#define HD 64
#define NCLUS 8
#define SCALE 0.125f
#define EPS 1e-6f
#define EPS_N (1e-6f/1024.0f)
#define SC_CAP 256

#define OUT_ELEMS (BB*NN*CC)                       // 1,048,576
#define MAP_ELEMS ((size_t)BB*NCLUS*HH*NN*NN)      // 134,217,728

// Map fill partition (float4 units). Total = MAP_ELEMS/4 = 33,554,432.
#define N4_TOTAL  ((size_t)33554432)
#define F_QKV     ((size_t)9437184)    // 144MB zeroed inside qkv kernel
#define F_ATTN    ((size_t)11534336)   // 176MB zeroed inside attn kernel
#define F_PROJ    ((size_t)5242880)    // 80MB zeroed inside proj kernel
#define F_REST    (N4_TOTAL - F_QKV - F_ATTN - F_PROJ)  // 112MB standalone
#define NF_QKV  128
#define NF_ATTN 192
#define NF_PROJ 128

// Scratch (static device globals; no allocation allowed)
__device__ float g_Q[BB*NN*CC];
__device__ float g_Kb[BB*NN*CC];
__device__ float g_V[BB*NN*CC];
__device__ float g_O[BB*NN*CC];
__device__ float g_colsum[BB*CC];
__device__ float g_csp[16][BB*CC];
__device__ int   g_mem[BB*NCLUS*NN];
__device__ int   g_cnt[BB*NCLUS];
__device__ float g_Sc[(size_t)BB*NCLUS*HH*SC_CAP*SC_CAP];

// ---------------------------------------------------------------------------
// Filler-block helper: zero a contiguous float4 chunk with streaming stores.
// ---------------------------------------------------------------------------
__device__ __forceinline__ void fill_chunk(float4* __restrict__ base,
                                           size_t s, size_t e)
{
    const float4 z = make_float4(0.f, 0.f, 0.f, 0.f);
    for (size_t i = s + threadIdx.x; i < e; i += 256)
        __stcs(&base[i], z);
}

__device__ __forceinline__ void filler_block(float4* __restrict__ map4,
                                             size_t fstart, size_t fcount,
                                             int f, int nf)
{
    const size_t chunk = (fcount + nf - 1) / nf;
    const size_t s = fstart + (size_t)f * chunk;
    size_t e = s + chunk;
    const size_t lim = fstart + fcount;
    if (e > lim) e = lim;
    if (s < e) fill_chunk(map4, s, e);
}

// ---------------------------------------------------------------------------
// Deterministic cluster compaction: one warp per (b,c).
// ---------------------------------------------------------------------------
__global__ void compact_kernel(const int* __restrict__ idx,
                               int* __restrict__ mem, int* __restrict__ cnt)
{
    const int bc = blockIdx.x;
    const int b = bc >> 3, c = bc & 7;
    const int lane = threadIdx.x;
    int pos = 0;
    for (int t0 = 0; t0 < NN; t0 += 32) {
        int t = t0 + lane;
        int v = idx[b * NN + t];
        unsigned ball = __ballot_sync(0xffffffffu, v == c);
        if (v == c) {
            int r = __popc(ball & ((1u << lane) - 1u));
            mem[bc * NN + pos + r] = t;
        }
        pos += __popc(ball);
    }
    if (lane == 0) cnt[bc] = pos;
}

// ---------------------------------------------------------------------------
// Standalone streaming fill for the leftover range.
// ---------------------------------------------------------------------------
__global__ void __launch_bounds__(256) fill_zero(float4* __restrict__ p, size_t n4)
{
    size_t i = (size_t)blockIdx.x * blockDim.x + threadIdx.x;
    const size_t stride = (size_t)gridDim.x * blockDim.x;
    const float4 z = make_float4(0.f, 0.f, 0.f, 0.f);
    for (; i < n4; i += stride)
        __stcs(&p[i], z);
}

// ---------------------------------------------------------------------------
// Compose member rows: full 4KB row = zeros + Sc values at member columns.
// Runs last; overwrites the zeroed member rows.
// ---------------------------------------------------------------------------
__global__ void __launch_bounds__(128) compose_rows(
    const float* __restrict__ Sc, const int* __restrict__ mem,
    const int* __restrict__ cnt, float* __restrict__ map)
{
    const int bch = blockIdx.y;
    const int bc = bch >> 3;
    int Mc = cnt[bc]; if (Mc > SC_CAP) Mc = SC_CAP;
    const int p = blockIdx.x;
    if (p >= Mc) return;

    __shared__ float rowbuf[NN];
    #pragma unroll
    for (int j = threadIdx.x; j < NN; j += 128) rowbuf[j] = 0.f;
    __syncthreads();

    const float* src = Sc + ((size_t)bch * SC_CAP + p) * SC_CAP;
    const int* memb = mem + bc * NN;
    for (int q = threadIdx.x; q < Mc; q += 128)
        rowbuf[memb[q]] = src[q];
    __syncthreads();

    const int i = memb[p];
    float4* dst = reinterpret_cast<float4*>(map + ((size_t)bch * NN + i) * NN);
    const float4* s4 = reinterpret_cast<const float4*>(rowbuf);
    #pragma unroll
    for (int j = threadIdx.x; j < NN / 4; j += 128)
        __stcs(&dst[j], s4[j]);
}

// ---------------------------------------------------------------------------
// TF32 helpers (3xTF32 split)
// ---------------------------------------------------------------------------
__device__ __forceinline__ void tf32_pair(float x, uint32_t& hi, uint32_t& lo)
{
    asm("cvt.rna.tf32.f32 %0, %1;" : "=r"(hi) : "f"(x));
    float r = x - __uint_as_float(hi);
    asm("cvt.rna.tf32.f32 %0, %1;" : "=r"(lo) : "f"(r));
}

__device__ __forceinline__ void mma8(float* c, const uint32_t* a, const uint32_t* b)
{
    asm volatile(
        "mma.sync.aligned.m16n8k8.row.col.f32.tf32.tf32.f32 "
        "{%0,%1,%2,%3}, {%4,%5,%6,%7}, {%8,%9}, {%0,%1,%2,%3};"
        : "+f"(c[0]), "+f"(c[1]), "+f"(c[2]), "+f"(c[3])
        : "r"(a[0]), "r"(a[1]), "r"(a[2]), "r"(a[3]), "r"(b[0]), "r"(b[1]));
}

// ---------------------------------------------------------------------------
// TF32 GEMM body: out[m,n] = sum_k X[m,k]*W[n,k] (+bias). K=N=512.
// ---------------------------------------------------------------------------
#define SMS 136

__device__ __forceinline__ void gemm_tf32_body(
    const float* __restrict__ X, const float* __restrict__ W,
    const float* __restrict__ bias, float* __restrict__ out,
    int m0, int n0, bool has_bias)
{
    __shared__ uint32_t As_h[16][SMS], As_l[16][SMS];
    __shared__ uint32_t Bs_h[16][SMS], Bs_l[16][SMS];

    const int tid  = threadIdx.x;
    const int lane = tid & 31;
    const int wid  = tid >> 5;
    const int warp_m = wid & 1;
    const int warp_n = wid >> 1;

    const int lr  = tid >> 1;
    const int lc0 = (tid & 1) * 8;

    float acc[4][4][4];
    #pragma unroll
    for (int f = 0; f < 4; f++)
        #pragma unroll
        for (int g = 0; g < 4; g++)
            #pragma unroll
            for (int e = 0; e < 4; e++) acc[f][g][e] = 0.f;

    for (int k0 = 0; k0 < 512; k0 += 16) {
        #pragma unroll
        for (int u = 0; u < 2; u++) {
            float4 va = *reinterpret_cast<const float4*>(&X[(size_t)(m0 + lr) * 512 + k0 + lc0 + u * 4]);
            float ea[4] = {va.x, va.y, va.z, va.w};
            float4 vb = *reinterpret_cast<const float4*>(&W[(size_t)(n0 + lr) * 512 + k0 + lc0 + u * 4]);
            float eb[4] = {vb.x, vb.y, vb.z, vb.w};
            #pragma unroll
            for (int j = 0; j < 4; j++) {
                int k = lc0 + u * 4 + j;
                uint32_t h, l;
                tf32_pair(ea[j], h, l);
                As_h[k][lr] = h; As_l[k][lr] = l;
                tf32_pair(eb[j], h, l);
                Bs_h[k][lr] = h; Bs_l[k][lr] = l;
            }
        }
        __syncthreads();

        #pragma unroll
        for (int ks = 0; ks < 2; ks++) {
            const int kb = ks * 8 + (lane & 3);
            uint32_t ah[4][4], al[4][4];
            #pragma unroll
            for (int f = 0; f < 4; f++) {
                int m = warp_m * 64 + f * 16 + (lane >> 2);
                ah[f][0] = As_h[kb][m];     ah[f][1] = As_h[kb][m + 8];
                ah[f][2] = As_h[kb + 4][m]; ah[f][3] = As_h[kb + 4][m + 8];
                al[f][0] = As_l[kb][m];     al[f][1] = As_l[kb][m + 8];
                al[f][2] = As_l[kb + 4][m]; al[f][3] = As_l[kb + 4][m + 8];
            }
            uint32_t bh[4][2], bl[4][2];
            #pragma unroll
            for (int g = 0; g < 4; g++) {
                int n = warp_n * 32 + g * 8 + (lane >> 2);
                bh[g][0] = Bs_h[kb][n]; bh[g][1] = Bs_h[kb + 4][n];
                bl[g][0] = Bs_l[kb][n]; bl[g][1] = Bs_l[kb + 4][n];
            }
            #pragma unroll
            for (int f = 0; f < 4; f++)
                #pragma unroll
                for (int g = 0; g < 4; g++) {
                    mma8(acc[f][g], ah[f], bh[g]);
                    mma8(acc[f][g], ah[f], bl[g]);
                    mma8(acc[f][g], al[f], bh[g]);
                }
        }
        __syncthreads();
    }

    #pragma unroll
    for (int f = 0; f < 4; f++) {
        const int m = m0 + warp_m * 64 + f * 16 + (lane >> 2);
        #pragma unroll
        for (int g = 0; g < 4; g++) {
            const int n = n0 + warp_n * 32 + g * 8 + (lane & 3) * 2;
            float b0 = 0.f, b1 = 0.f;
            if (has_bias) { b0 = bias[n]; b1 = bias[n + 1]; }
            float2 v0 = make_float2(acc[f][g][0] + b0, acc[f][g][1] + b1);
            float2 v1 = make_float2(acc[f][g][2] + b0, acc[f][g][3] + b1);
            *reinterpret_cast<float2*>(&out[(size_t)m * 512 + n]) = v0;
            *reinterpret_cast<float2*>(&out[(size_t)(m + 8) * 512 + n]) = v1;
        }
    }
}

// QKV GEMM + fused map zero-fill. 1D grid: [0,192) compute, rest fillers.
__global__ void __launch_bounds__(256) gemm_qkv_tf32(
    const float* __restrict__ X,
    const float* __restrict__ Wq, const float* __restrict__ Wk, const float* __restrict__ Wv,
    float* __restrict__ Qo, float* __restrict__ Ko, float* __restrict__ Vo,
    float4* __restrict__ map4, int nf)
{
    const int bid = blockIdx.x;
    if (bid >= 192) {
        filler_block(map4, 0, F_QKV, bid - 192, nf);
        return;
    }
    const int z = bid / 64, r = bid % 64;
    const float* W = (z == 0) ? Wq : (z == 1) ? Wk : Wv;
    float* out     = (z == 0) ? Qo : (z == 1) ? Ko : Vo;
    gemm_tf32_body(X, W, nullptr, out, (r >> 2) * 128, (r & 3) * 128, false);
}

// Proj GEMM + fused map zero-fill. [0,64) compute.
__global__ void __launch_bounds__(256) gemm_proj_tf32(
    const float* __restrict__ X, const float* __restrict__ W,
    const float* __restrict__ bias, float* __restrict__ out,
    float4* __restrict__ map4, int nf)
{
    const int bid = blockIdx.x;
    if (bid >= 64) {
        filler_block(map4, F_QKV + F_ATTN, F_PROJ, bid - 64, nf);
        return;
    }
    gemm_tf32_body(X, W, bias, out, (bid >> 2) * 128, (bid & 3) * 128, true);
}

// ---------------------------------------------------------------------------
// Column sums of V, two-stage deterministic. Stage 1: 64 blocks, 64-row slabs.
// ---------------------------------------------------------------------------
__global__ void __launch_bounds__(256) colsum_part(const float* __restrict__ V,
                                                   float (*__restrict__ csp)[BB*CC])
{
    const int b = blockIdx.y;
    const int z = blockIdx.z;
    const int c = blockIdx.x * 256 + threadIdx.x;
    const float* base = V + ((size_t)b * NN + z * 64) * CC + c;
    float s = 0.0f;
    #pragma unroll 8
    for (int n = 0; n < 64; n++)
        s += base[(size_t)n * CC];
    csp[z][b * CC + c] = s;
}

__global__ void __launch_bounds__(256) colsum_final(const float (*__restrict__ csp)[BB*CC],
                                                    float* __restrict__ cs)
{
    const int i = blockIdx.x * 256 + threadIdx.x;
    float s = 0.0f;
    #pragma unroll
    for (int z = 0; z < 16; z++) s += csp[z][i];
    cs[i] = s;
}

// ---------------------------------------------------------------------------
// Fused cluster-block attention + fused map zero-fill.
// 1D grid: [0,512) compute (ti = bid&3, bch = bid>>2), rest fillers.
// ---------------------------------------------------------------------------
extern __shared__ float sm_dyn[];
__global__ void cluster_attn(const float* __restrict__ Q, const float* __restrict__ K,
                             const float* __restrict__ V,
                             const int* __restrict__ mem, const int* __restrict__ cnt,
                             const float* __restrict__ cs,
                             float* __restrict__ Sc, float* __restrict__ O,
                             float4* __restrict__ map4, int nf)
{
    const int bid = blockIdx.x;
    if (bid >= 512) {
        filler_block(map4, F_QKV, F_ATTN, bid - 512, nf);
        return;
    }
    const int bch = bid >> 2;
    const int ti  = bid & 3;
    const int h  = bch & 7;
    const int bc = bch >> 3;
    const int b  = bc >> 3;
    const int Mc = cnt[bc];
    if (ti * 64 >= Mc) return;

    float* Qs = sm_dyn;                 // [k][i], 64x64
    float* Ks = Qs + 4096;              // [k][j]
    float* Vs = Ks + 4096;              // [j][d]
    float* Es = Vs + 4096;              // [i][j], 64x65

    const int t = threadIdx.x;
    const int row = t >> 2, quad = t & 3;
    const int tx = t & 15, ty = t >> 4;

    const int* memb = mem + bc * NN;

    const int il_row = ti * 64 + row;
    const int gi_row = (il_row < Mc) ? memb[il_row] : -1;
    {
        const float* qb = (gi_row >= 0)
            ? Q + ((size_t)(b * NN + gi_row)) * CC + h * HD : nullptr;
        #pragma unroll
        for (int u = 0; u < 4; u++) {
            int k = quad * 16 + u * 4;
            float4 qv = qb ? *reinterpret_cast<const float4*>(qb + k)
                           : make_float4(0.f, 0.f, 0.f, 0.f);
            Qs[(k+0)*64 + row] = qv.x; Qs[(k+1)*64 + row] = qv.y;
            Qs[(k+2)*64 + row] = qv.z; Qs[(k+3)*64 + row] = qv.w;
        }
    }

    int gi_r[4];
    #pragma unroll
    for (int r = 0; r < 4; r++) {
        int il = ti * 64 + ty * 4 + r;
        gi_r[r] = (il < Mc) ? memb[il] : -1;
    }

    float acc2[4][4] = {};
    float rsum[4] = {0.f, 0.f, 0.f, 0.f};

    const int njt = (Mc + 63) >> 6;
    for (int jb = 0; jb < njt; jb++) {
        const int jl_row = jb * 64 + row;
        const int gj_row = (jl_row < Mc) ? memb[jl_row] : -1;
        const float* kb = (gj_row >= 0)
            ? K + ((size_t)(b * NN + gj_row)) * CC + h * HD : nullptr;
        const float* vb = (gj_row >= 0)
            ? V + ((size_t)(b * NN + gj_row)) * CC + h * HD : nullptr;
        #pragma unroll
        for (int u = 0; u < 4; u++) {
            int k = quad * 16 + u * 4;
            float4 kv = kb ? *reinterpret_cast<const float4*>(kb + k)
                           : make_float4(0.f, 0.f, 0.f, 0.f);
            Ks[(k+0)*64 + row] = kv.x; Ks[(k+1)*64 + row] = kv.y;
            Ks[(k+2)*64 + row] = kv.z; Ks[(k+3)*64 + row] = kv.w;
            float4 vv = vb ? *reinterpret_cast<const float4*>(vb + k)
                           : make_float4(0.f, 0.f, 0.f, 0.f);
            *reinterpret_cast<float4*>(&Vs[row * 64 + k]) = vv;
        }
        __syncthreads();

        // gemm1: S = Q K^T
        float acc[4][4] = {};
        #pragma unroll
        for (int kk = 0; kk < 64; kk++) {
            float4 af = *reinterpret_cast<const float4*>(&Qs[kk*64 + ty*4]);
            float4 bf = *reinterpret_cast<const float4*>(&Ks[kk*64 + tx*4]);
            float ar[4] = {af.x, af.y, af.z, af.w};
            float br[4] = {bf.x, bf.y, bf.z, bf.w};
            #pragma unroll
            for (int r = 0; r < 4; r++)
                #pragma unroll
                for (int c = 0; c < 4; c++)
                    acc[r][c] += ar[r] * br[c];
        }

        // epilogue: scale, exp, compact-store, stage E
        #pragma unroll
        for (int r = 0; r < 4; r++) {
            const int pi = ti * 64 + ty * 4 + r;
            const bool vr = (gi_r[r] >= 0);
            #pragma unroll
            for (int c = 0; c < 4; c++) {
                const int qj = jb * 64 + tx * 4 + c;
                const bool valid = vr && (qj < Mc);
                float s = acc[r][c] * SCALE;
                float e = (valid && s != 0.0f) ? __expf(s) : 0.0f;
                if (valid && Sc != nullptr)
                    Sc[((size_t)bch * SC_CAP + pi) * SC_CAP + qj] = s;
                Es[(ty*4 + r) * 65 + tx*4 + c] = e;
                rsum[r] += e;
            }
        }
        __syncthreads();

        // gemm2: acc2 += E @ V
        #pragma unroll
        for (int jj = 0; jj < 64; jj++) {
            float ar[4];
            #pragma unroll
            for (int r = 0; r < 4; r++) ar[r] = Es[(ty*4 + r) * 65 + jj];
            float4 bv = *reinterpret_cast<const float4*>(&Vs[jj * 64 + tx*4]);
            float br[4] = {bv.x, bv.y, bv.z, bv.w};
            #pragma unroll
            for (int r = 0; r < 4; r++)
                #pragma unroll
                for (int c = 0; c < 4; c++)
                    acc2[r][c] += ar[r] * br[c];
        }
        __syncthreads();
    }

    #pragma unroll
    for (int r = 0; r < 4; r++) {
        #pragma unroll
        for (int o = 1; o < 16; o <<= 1)
            rsum[r] += __shfl_xor_sync(0xffffffffu, rsum[r], o);
    }

    #pragma unroll
    for (int r = 0; r < 4; r++) {
        if (gi_r[r] < 0) continue;
        float inv = 1.0f / (rsum[r] + EPS);
        float4 o;
        float* po = &o.x;
        #pragma unroll
        for (int c = 0; c < 4; c++) {
            int d = tx * 4 + c;
            po[c] = (acc2[r][c] + EPS_N * cs[b * CC + h * HD + d]) * inv;
        }
        *reinterpret_cast<float4*>(&O[((size_t)(b * NN + gi_r[r])) * CC + h * HD + tx*4]) = o;
    }
}

// ---------------------------------------------------------------------------
extern "C" void kernel_launch(void* const* d_in, const int* in_sizes, int n_in,
                              void* d_out, int out_size)
{
    const float* x_token = nullptr;
    const int*   idx     = nullptr;
    const float* Wmat[4] = {nullptr, nullptr, nullptr, nullptr};  // Wq,Wk,Wv,Wproj
    const float* bproj   = nullptr;
    int nW = 0;
    for (int i = 0; i < n_in; i++) {
        int s = in_sizes[i];
        if (s == OUT_ELEMS && !x_token)      x_token = (const float*)d_in[i];
        else if (s == 262144 && nW < 4)      Wmat[nW++] = (const float*)d_in[i];
        else if (s == 2048 && !idx)          idx = (const int*)d_in[i];
        else if (s == 512 && !bproj)         bproj = (const float*)d_in[i];
    }

    float *pQ, *pK, *pV, *pO, *pCS, *pSc;
    float (*pCSP)[BB*CC];
    int *pMem, *pCnt;
    cudaGetSymbolAddress((void**)&pQ,   g_Q);
    cudaGetSymbolAddress((void**)&pK,   g_Kb);
    cudaGetSymbolAddress((void**)&pV,   g_V);
    cudaGetSymbolAddress((void**)&pO,   g_O);
    cudaGetSymbolAddress((void**)&pCS,  g_colsum);
    cudaGetSymbolAddress((void**)&pCSP, g_csp);
    cudaGetSymbolAddress((void**)&pMem, g_mem);
    cudaGetSymbolAddress((void**)&pCnt, g_cnt);
    cudaGetSymbolAddress((void**)&pSc,  g_Sc);

    float* out = (float*)d_out;
    const bool has_map = ((size_t)out_size >= OUT_ELEMS + MAP_ELEMS);
    float* map = has_map ? out + OUT_ELEMS : nullptr;
    float4* map4 = reinterpret_cast<float4*>(map);

    static bool inited = false;
    if (!inited) {
        const int SMEM_BYTES = (3 * 4096 + 64 * 65) * sizeof(float);  // 65792
        cudaFuncSetAttribute(cluster_attn,
                             cudaFuncAttributeMaxDynamicSharedMemorySize, SMEM_BYTES);
        inited = true;
    }
    const int SMEM_BYTES = (3 * 4096 + 64 * 65) * sizeof(float);

    const int nf1 = has_map ? NF_QKV  : 0;
    const int nf2 = has_map ? NF_ATTN : 0;
    const int nf3 = has_map ? NF_PROJ : 0;

    // Single stream, fused fill: each heavy kernel's grid carries filler
    // blocks that stream-zero a static slice of the map while compute blocks
    // run on tensor/FMA pipes (co-residency guaranteed within one grid).
    compact_kernel<<<BB * NCLUS, 32>>>(idx, pMem, pCnt);

    gemm_qkv_tf32<<<192 + nf1, 256>>>(x_token, Wmat[0], Wmat[1], Wmat[2],
                                      pQ, pK, pV, map4, nf1);

    colsum_part<<<dim3(CC / 256, BB, 16), 256>>>(pV, pCSP);
    colsum_final<<<(BB * CC) / 256, 256>>>(pCSP, pCS);

    cluster_attn<<<512 + nf2, 256, SMEM_BYTES>>>(
        pQ, pK, pV, pMem, pCnt, pCS, has_map ? pSc : nullptr, pO, map4, nf2);

    gemm_proj_tf32<<<64 + nf3, 256>>>(pO, Wmat[3], bproj, out, map4, nf3);

    if (has_map) {
        // Leftover slice, then overwrite member rows with composed data.
        fill_zero<<<1024, 256>>>(map4 + (F_QKV + F_ATTN + F_PROJ), F_REST);
        compose_rows<<<dim3(SC_CAP, BB * NCLUS * HH), 128>>>(pSc, pMem, pCnt, map);
    }
}